// round 1
// baseline (speedup 1.0000x reference)
#include <cuda_runtime.h>

// Problem constants
#define S_TOT   14
#define NRX     16
#define NTX     4
#define BF_TOT  (16 * 4096)      // B * F = 65536
#define PAIRS   6                // 12 data symbols -> 6 STBC pairs
#define NBITS0  3145728          // BF_TOT * 48
#define NGAIN   786432           // BF_TOT * 12

__device__ __forceinline__ float2 cmul (float2 a, float2 b){ return make_float2(a.x*b.x - a.y*b.y, a.x*b.y + a.y*b.x); }
__device__ __forceinline__ float2 cmulc(float2 a, float2 b){ /* conj(a)*b */ return make_float2(a.x*b.x + a.y*b.y, a.x*b.y - a.y*b.x); }
__device__ __forceinline__ float2 cadd (float2 a, float2 b){ return make_float2(a.x+b.x, a.y+b.y); }
__device__ __forceinline__ float2 csub (float2 a, float2 b){ return make_float2(a.x-b.x, a.y-b.y); }
__device__ __forceinline__ float2 cscl (float2 a, float s){ return make_float2(a.x*s, a.y*s); }
__device__ __forceinline__ float2 cconj(float2 a){ return make_float2(a.x, -a.y); }

// 16-QAM Gray hard decision (max-log equivalent). Returns constellation point and
// 4-bit label nibble: b0=I-sign, b1=Q-sign, b2=I-mag, b3=Q-mag (b0 = label MSB).
__device__ __forceinline__ void hd16(float2 y, float2& pt, int& bits){
    const float C1 = 0.31622776601683794f;   // 1/sqrt(10)
    const float C3 = 0.9486832980505138f;    // 3/sqrt(10)
    const float T  = 0.6324555320336759f;    // 2/sqrt(10)
    int b0 = (y.x < 0.0f);
    int b1 = (y.y < 0.0f);
    int b2 = (fabsf(y.x) > T);
    int b3 = (fabsf(y.y) > T);
    float xi = b2 ? C3 : C1; if (b0) xi = -xi;
    float xq = b3 ? C3 : C1; if (b1) xq = -xq;
    pt = make_float2(xi, xq);
    bits = b0 | (b1 << 1) | (b2 << 2) | (b3 << 3);
}

#define RED16(v) do { \
    v += __shfl_xor_sync(0xffffffffu, v, 1);  \
    v += __shfl_xor_sync(0xffffffffu, v, 2);  \
    v += __shfl_xor_sync(0xffffffffu, v, 4);  \
    v += __shfl_xor_sync(0xffffffffu, v, 8);  \
} while (0)

__global__ void __launch_bounds__(256)
mc_ncjt_kernel(const float* __restrict__ ryR, const float* __restrict__ ryI,
               const float* __restrict__ hR,  const float* __restrict__ hI,
               float* __restrict__ out)
{
    const int lane = threadIdx.x & 31;
    const int warp = blockIdx.x * (blockDim.x >> 5) + (threadIdx.x >> 5);
    const int half = lane >> 4;       // which pair within the warp
    const int ant  = lane & 15;       // RX antenna = lane within half-warp

    const int P  = warp * 2 + half;   // global STBC-pair index, exact grid
    const int bf = P / PAIRS;
    const int p  = P - bf * PAIRS;

    // data-symbol pairs: (0,1)(3,4)(5,6)(7,8)(9,10)(12,13) -> sA = 2p + [p>=1] + [p>=5]
    const int sA = 2*p + (p >= 1) + (p >= 5);
    const int sB = sA + 1;

    // ---- load this antenna's data (all later passes run from registers) ----
    const float4* hR4 = (const float4*)hR;
    const float4* hI4 = (const float4*)hI;
    const size_t h4base = (size_t)bf * 224;          // bf * S*NRX*NTX / 4
    float4 hrA = hR4[h4base + (size_t)sA*16 + ant];
    float4 hiA = hI4[h4base + (size_t)sA*16 + ant];
    float4 hrB = hR4[h4base + (size_t)sB*16 + ant];
    float4 hiB = hI4[h4base + (size_t)sB*16 + ant];
    const size_t rybase = (size_t)bf * 224;          // bf * S*NRX
    float2 yA = make_float2(ryR[rybase + sA*16 + ant], ryI[rybase + sA*16 + ant]);
    float2 yB = make_float2(ryR[rybase + sB*16 + ant], ryI[rybase + sB*16 + ant]);

    // averaged channel for this antenna: a,b = TX0,1 ; c,d = TX2,3
    float2 a = make_float2(0.5f*(hrA.x+hrB.x), 0.5f*(hiA.x+hiB.x));
    float2 b = make_float2(0.5f*(hrA.y+hrB.y), 0.5f*(hiA.y+hiB.y));
    float2 c = make_float2(0.5f*(hrA.z+hrB.z), 0.5f*(hiA.z+hiB.z));
    float2 d = make_float2(0.5f*(hrA.w+hrB.w), 0.5f*(hiA.w+hiB.w));

    // ---- per-lane Gram/rhs contributions (G has Alamouti structure) ----
    float alpha = a.x*a.x + a.y*a.y + b.x*b.x + b.y*b.y;
    float beta  = c.x*c.x + c.y*c.y + d.x*d.x + d.y*d.y;
    float2 gam = cadd(cmulc(a, c), cmul(b, cconj(d)));   // conj(a)*c + b*conj(d)
    float2 del = csub(cmulc(a, d), cmul(b, cconj(c)));   // conj(a)*d - b*conj(c)
    float2 z2 = cconj(yB);
    float2 u0 = cadd(cmulc(a, yA), cmul(b, z2));
    float2 u1 = csub(cmulc(b, yA), cmul(a, z2));
    float2 u2 = cadd(cmulc(c, yA), cmul(d, z2));
    float2 u3 = csub(cmulc(d, yA), cmul(c, z2));

    RED16(alpha); RED16(beta);
    RED16(gam.x); RED16(gam.y); RED16(del.x); RED16(del.y);
    RED16(u0.x);  RED16(u0.y);  RED16(u1.x);  RED16(u1.y);
    RED16(u2.x);  RED16(u2.y);  RED16(u3.x);  RED16(u3.y);

    // ---- closed-form Schur solve of the structured 4x4 system ----
    const float e      = gam.x*gam.x + gam.y*gam.y + del.x*del.x + del.y*del.y;
    const float invden = 1.0f / (alpha * beta - e);
    const float invA   = 1.0f / alpha;
    float2 t2 = csub(cscl(u2, alpha), csub(cmulc(gam, u0), cmul(del, u1)));
    float2 t3 = csub(cscl(u3, alpha), cadd(cmulc(del, u0), cmul(gam, u1)));
    float2 s2 = cscl(t2, invden);
    float2 s3 = cscl(t3, invden);
    float2 s0 = cscl(csub(u0, cadd(cmul(gam, s2), cmul(del, s3))), invA);
    float2 s1 = cscl(cadd(u1, csub(cmul(cconj(del), s2), cmul(cconj(gam), s3))), invA);

    const bool c0 = (alpha >= beta);

    float2 px0, px1, px2, px3; int ib0, ib1, ib2, ib3;
    hd16(s0, px0, ib0); hd16(s1, px1, ib1);
    hd16(s2, px2, ib2); hd16(s3, px3, ib3);

    float2 bx0 = c0 ? px0 : px2;     // better-stream decisions (sym A, sym B)
    float2 bx1 = c0 ? px1 : px3;

    // ---- SIC: cancel better stream (per-symbol channels), re-decode worse ----
    float2 cbA0, cbA1, cbB0, cbB1, g0, g1;
    if (c0) {
        cbA0 = make_float2(hrA.x, hiA.x); cbA1 = make_float2(hrA.y, hiA.y);
        cbB0 = make_float2(hrB.x, hiB.x); cbB1 = make_float2(hrB.y, hiB.y);
        g0 = c; g1 = d;                 // worse = averaged TX2/3
    } else {
        cbA0 = make_float2(hrA.z, hiA.z); cbA1 = make_float2(hrA.w, hiA.w);
        cbB0 = make_float2(hrB.z, hiB.z); cbB1 = make_float2(hrB.w, hiB.w);
        g0 = a; g1 = b;                 // worse = averaged TX0/1
    }
    float2 eA = cadd(cmul(cbA0, bx0), cmul(cbA1, bx1));
    float2 mcbx1 = make_float2(-bx1.x, bx1.y);     // -conj(bx1)
    float2 cbx0  = cconj(bx0);
    float2 eB = cadd(cmul(cbB0, mcbx1), cmul(cbB1, cbx0));
    float2 rnA = csub(yA, eA);
    float2 rnBc = cconj(csub(yB, eB));
    float2 t0 = cadd(cmulc(g0, rnA), cmul(g1, rnBc));
    float2 t1 = csub(cmulc(g1, rnA), cmul(g0, rnBc));
    RED16(t0.x); RED16(t0.y); RED16(t1.x); RED16(t1.y);

    const float invG = 1.0f / (c0 ? beta : alpha);
    float2 pn0, pn1; int ibn0, ibn1;
    hd16(cscl(t0, invG), pn0, ibn0);
    hd16(cscl(t1, invG), pn1, ibn1);

    // final stream assignments
    const int bb0 = c0 ? ib0 : ib2;   // better bits sym A
    const int bb1 = c0 ? ib1 : ib3;   // better bits sym B
    const int b0A = c0 ? bb0  : ibn0; // bits0 (stream 0)
    const int b0B = c0 ? bb1  : ibn1;
    const int b1A = c0 ? ibn0 : bb0;  // bits1 (stream 1)
    const int b1B = c0 ? ibn1 : bb1;

    // ---- outputs: bits0 | bits1 | gains0 | gains1 | nvar ----
    float* bits0 = out;
    float* bits1 = out + NBITS0;
    float* g0out = out + 2 * NBITS0;
    float* g1out = out + 2 * NBITS0 + NGAIN;

    const int sym0 = 2 * p;   // position within the 12 data symbols
    if (ant < 8) {
        int sym = ant >> 2, bit = ant & 3;
        int nib = sym ? b0B : b0A;
        bits0[(size_t)bf*48 + (sym0+sym)*4 + bit] = (float)((nib >> bit) & 1);
    } else {
        int l2 = ant - 8;
        int sym = l2 >> 2, bit = l2 & 3;
        int nib = sym ? b1B : b1A;
        bits1[(size_t)bf*48 + (sym0+sym)*4 + bit] = (float)((nib >> bit) & 1);
    }
    if (ant < 2)      g0out[(size_t)bf*12 + sym0 + ant]       = alpha;
    else if (ant < 4) g1out[(size_t)bf*12 + sym0 + (ant - 2)] = beta;

    if (blockIdx.x == 0 && threadIdx.x == 0)
        out[2 * (NBITS0 + NGAIN)] = 0.4f;    // nvar scalar
}

extern "C" void kernel_launch(void* const* d_in, const int* in_sizes, int n_in,
                              void* d_out, int out_size) {
    const float* ryR = (const float*)d_in[0];
    const float* ryI = (const float*)d_in[1];
    const float* hR  = (const float*)d_in[2];
    const float* hI  = (const float*)d_in[3];
    float* out = (float*)d_out;

    // total pairs = 65536*6 = 393216; 2 pairs/warp, 8 warps/block -> 24576 blocks
    const int total_pairs = BF_TOT * PAIRS;
    const int blocks = total_pairs / 16;   // 16 pairs per 256-thread block
    mc_ncjt_kernel<<<blocks, 256>>>(ryR, ryI, hR, hI, out);
}

// round 3
// speedup vs baseline: 1.1587x; 1.1587x over previous
#include <cuda_runtime.h>

// Problem constants
#define BF_TOT  (16 * 4096)      // B * F = 65536
#define PAIRS   6                // 12 data symbols -> 6 STBC pairs
#define NBITS0  3145728          // BF_TOT * 48
#define NGAIN   786432           // BF_TOT * 12

__device__ __forceinline__ float2 cmul (float2 a, float2 b){ return make_float2(a.x*b.x - a.y*b.y, a.x*b.y + a.y*b.x); }
__device__ __forceinline__ float2 cmulc(float2 a, float2 b){ /* conj(a)*b */ return make_float2(a.x*b.x + a.y*b.y, a.x*b.y - a.y*b.x); }
__device__ __forceinline__ float2 cadd (float2 a, float2 b){ return make_float2(a.x+b.x, a.y+b.y); }
__device__ __forceinline__ float2 csub (float2 a, float2 b){ return make_float2(a.x-b.x, a.y-b.y); }
__device__ __forceinline__ float2 cscl (float2 a, float s){ return make_float2(a.x*s, a.y*s); }
__device__ __forceinline__ float2 cconj(float2 a){ return make_float2(a.x, -a.y); }

// 16-QAM Gray hard decision (max-log equivalent). Returns constellation point and
// 4-bit label nibble: b0=I-sign, b1=Q-sign, b2=I-mag, b3=Q-mag (b0 = label MSB).
__device__ __forceinline__ void hd16(float2 y, float2& pt, int& bits){
    const float C1 = 0.31622776601683794f;   // 1/sqrt(10)
    const float C3 = 0.9486832980505138f;    // 3/sqrt(10)
    const float T  = 0.6324555320336759f;    // 2/sqrt(10)
    int b0 = (y.x < 0.0f);
    int b1 = (y.y < 0.0f);
    int b2 = (fabsf(y.x) > T);
    int b3 = (fabsf(y.y) > T);
    float xi = b2 ? C3 : C1; if (b0) xi = -xi;
    float xq = b3 ? C3 : C1; if (b1) xq = -xq;
    pt = make_float2(xi, xq);
    bits = b0 | (b1 << 1) | (b2 << 2) | (b3 << 3);
}

// 3-step xor butterfly over each 8-lane group (result broadcast within group)
#define RED8(v) do { \
    v += __shfl_xor_sync(0xffffffffu, v, 1);  \
    v += __shfl_xor_sync(0xffffffffu, v, 2);  \
    v += __shfl_xor_sync(0xffffffffu, v, 4);  \
} while (0)

// Per-antenna Gram/rhs accumulation. hrA/hiA/hrB/hiB = raw channel float4s
// (TX0..3 in xyzw); yA/yB received symbols. Accumulates into the 22 sums.
#define GRAM_ACC(hrA_, hiA_, hrB_, hiB_, yA_, yB_) do {                         \
    float2 a_ = make_float2(0.5f*((hrA_).x+(hrB_).x), 0.5f*((hiA_).x+(hiB_).x)); \
    float2 b_ = make_float2(0.5f*((hrA_).y+(hrB_).y), 0.5f*((hiA_).y+(hiB_).y)); \
    float2 c_ = make_float2(0.5f*((hrA_).z+(hrB_).z), 0.5f*((hiA_).z+(hiB_).z)); \
    float2 d_ = make_float2(0.5f*((hrA_).w+(hrB_).w), 0.5f*((hiA_).w+(hiB_).w)); \
    alpha += a_.x*a_.x + a_.y*a_.y + b_.x*b_.x + b_.y*b_.y;                      \
    beta  += c_.x*c_.x + c_.y*c_.y + d_.x*d_.x + d_.y*d_.y;                      \
    gam = cadd(gam, cadd(cmulc(a_, c_), cmul(b_, cconj(d_))));                   \
    del = cadd(del, csub(cmulc(a_, d_), cmul(b_, cconj(c_))));                   \
    float2 z2_ = cconj(yB_);                                                     \
    u0 = cadd(u0, cadd(cmulc(a_, (yA_)), cmul(b_, z2_)));                        \
    u1 = cadd(u1, csub(cmulc(b_, (yA_)), cmul(a_, z2_)));                        \
    u2 = cadd(u2, cadd(cmulc(c_, (yA_)), cmul(d_, z2_)));                        \
    u3 = cadd(u3, csub(cmulc(d_, (yA_)), cmul(c_, z2_)));                        \
} while (0)

// Per-antenna SIC: cancel better-stream contribution (per-symbol channels),
// Alamouti-combine residual with averaged worse channel. Accumulates t0,t1.
#define SIC_ACC(hrA_, hiA_, hrB_, hiB_, yA_, yB_) do {                           \
    float2 cbA0_, cbA1_, cbB0_, cbB1_, g0_, g1_;                                 \
    if (c0) {                                                                    \
        cbA0_ = make_float2((hrA_).x, (hiA_).x); cbA1_ = make_float2((hrA_).y, (hiA_).y); \
        cbB0_ = make_float2((hrB_).x, (hiB_).x); cbB1_ = make_float2((hrB_).y, (hiB_).y); \
        g0_ = make_float2(0.5f*((hrA_).z+(hrB_).z), 0.5f*((hiA_).z+(hiB_).z));   \
        g1_ = make_float2(0.5f*((hrA_).w+(hrB_).w), 0.5f*((hiA_).w+(hiB_).w));   \
    } else {                                                                     \
        cbA0_ = make_float2((hrA_).z, (hiA_).z); cbA1_ = make_float2((hrA_).w, (hiA_).w); \
        cbB0_ = make_float2((hrB_).z, (hiB_).z); cbB1_ = make_float2((hrB_).w, (hiB_).w); \
        g0_ = make_float2(0.5f*((hrA_).x+(hrB_).x), 0.5f*((hiA_).x+(hiB_).x));   \
        g1_ = make_float2(0.5f*((hrA_).y+(hrB_).y), 0.5f*((hiA_).y+(hiB_).y));   \
    }                                                                            \
    float2 eA_ = cadd(cmul(cbA0_, bx0), cmul(cbA1_, bx1));                       \
    float2 eB_ = cadd(cmul(cbB0_, mcbx1), cmul(cbB1_, cbx0));                    \
    float2 rnA_ = csub((yA_), eA_);                                              \
    float2 rnBc_ = cconj(csub((yB_), eB_));                                      \
    t0 = cadd(t0, cadd(cmulc(g0_, rnA_), cmul(g1_, rnBc_)));                     \
    t1 = cadd(t1, csub(cmulc(g1_, rnA_), cmul(g0_, rnBc_)));                     \
} while (0)

__global__ void __launch_bounds__(256)
mc_ncjt_kernel(const float* __restrict__ ryR, const float* __restrict__ ryI,
               const float* __restrict__ hR,  const float* __restrict__ hI,
               float* __restrict__ out)
{
    const int lane = threadIdx.x & 31;
    const int warp = blockIdx.x * (blockDim.x >> 5) + (threadIdx.x >> 5);
    const int q    = lane >> 3;       // which pair within the warp (4 pairs/warp)
    const int j    = lane & 7;        // 8 lanes per pair; lane owns antennas j and j+8

    const int P  = warp * 4 + q;      // global STBC-pair index, exact grid
    const int bf = P / PAIRS;
    const int p  = P - bf * PAIRS;

    // data-symbol pairs: (0,1)(3,4)(5,6)(7,8)(9,10)(12,13)
    const int sA = 2*p + (p >= 1) + (p >= 5);
    const int sB = sA + 1;

    // ---- load both antennas' data; everything later runs from registers ----
    const float4* hR4 = (const float4*)hR;
    const float4* hI4 = (const float4*)hI;
    const size_t h4base = (size_t)bf * 224;          // bf * S*NRX*NTX / 4
    const size_t iA = h4base + (size_t)sA*16 + j;
    const size_t iB = h4base + (size_t)sB*16 + j;
    float4 hrA0 = hR4[iA],     hrA1 = hR4[iA + 8];
    float4 hiA0 = hI4[iA],     hiA1 = hI4[iA + 8];
    float4 hrB0 = hR4[iB],     hrB1 = hR4[iB + 8];
    float4 hiB0 = hI4[iB],     hiB1 = hI4[iB + 8];
    const size_t rb = (size_t)bf * 224;              // bf * S*NRX
    float2 yA0 = make_float2(ryR[rb + sA*16 + j],     ryI[rb + sA*16 + j]);
    float2 yA1 = make_float2(ryR[rb + sA*16 + j + 8], ryI[rb + sA*16 + j + 8]);
    float2 yB0 = make_float2(ryR[rb + sB*16 + j],     ryI[rb + sB*16 + j]);
    float2 yB1 = make_float2(ryR[rb + sB*16 + j + 8], ryI[rb + sB*16 + j + 8]);

    // ---- Gram/rhs sums over this lane's 2 antennas ----
    float alpha = 0.f, beta = 0.f;
    float2 gam = make_float2(0,0), del = make_float2(0,0);
    float2 u0 = make_float2(0,0), u1 = make_float2(0,0);
    float2 u2 = make_float2(0,0), u3 = make_float2(0,0);
    GRAM_ACC(hrA0, hiA0, hrB0, hiB0, yA0, yB0);
    GRAM_ACC(hrA1, hiA1, hrB1, hiB1, yA1, yB1);

    // ---- 8-lane reductions (broadcast within pair group) ----
    RED8(alpha); RED8(beta);
    RED8(gam.x); RED8(gam.y); RED8(del.x); RED8(del.y);
    RED8(u0.x);  RED8(u0.y);  RED8(u1.x);  RED8(u1.y);
    RED8(u2.x);  RED8(u2.y);  RED8(u3.x);  RED8(u3.y);

    // ---- closed-form Schur solve of the structured 4x4 system ----
    const float e      = gam.x*gam.x + gam.y*gam.y + del.x*del.x + del.y*del.y;
    const float invden = 1.0f / (alpha * beta - e);
    const float invA   = 1.0f / alpha;
    float2 t2 = csub(cscl(u2, alpha), csub(cmulc(gam, u0), cmul(del, u1)));
    float2 t3 = csub(cscl(u3, alpha), cadd(cmulc(del, u0), cmul(gam, u1)));
    float2 s2 = cscl(t2, invden);
    float2 s3 = cscl(t3, invden);
    float2 s0 = cscl(csub(u0, cadd(cmul(gam, s2), cmul(del, s3))), invA);
    float2 s1 = cscl(cadd(u1, csub(cmul(cconj(del), s2), cmul(cconj(gam), s3))), invA);

    const bool c0 = (alpha >= beta);

    float2 px0, px1, px2, px3; int ib0, ib1, ib2, ib3;
    hd16(s0, px0, ib0); hd16(s1, px1, ib1);
    hd16(s2, px2, ib2); hd16(s3, px3, ib3);

    float2 bx0 = c0 ? px0 : px2;     // better-stream decisions (sym A, sym B)
    float2 bx1 = c0 ? px1 : px3;
    float2 mcbx1 = make_float2(-bx1.x, bx1.y);     // -conj(bx1)
    float2 cbx0  = cconj(bx0);

    // ---- SIC over this lane's 2 antennas, then reduce ----
    float2 t0 = make_float2(0,0), t1 = make_float2(0,0);
    SIC_ACC(hrA0, hiA0, hrB0, hiB0, yA0, yB0);
    SIC_ACC(hrA1, hiA1, hrB1, hiB1, yA1, yB1);
    RED8(t0.x); RED8(t0.y); RED8(t1.x); RED8(t1.y);

    const float invG = 1.0f / (c0 ? beta : alpha);
    float2 pn0, pn1; int ibn0, ibn1;
    hd16(cscl(t0, invG), pn0, ibn0);
    hd16(cscl(t1, invG), pn1, ibn1);

    // final stream assignments
    const int bb0 = c0 ? ib0 : ib2;   // better bits sym A
    const int bb1 = c0 ? ib1 : ib3;   // better bits sym B
    const int b0A = c0 ? bb0  : ibn0; // bits0 (stream 0)
    const int b0B = c0 ? bb1  : ibn1;
    const int b1A = c0 ? ibn0 : bb0;  // bits1 (stream 1)
    const int b1B = c0 ? ibn1 : bb1;

    // ---- outputs: bits0 | bits1 | gains0 | gains1 | nvar ----
    float* bits0 = out;
    float* bits1 = out + NBITS0;
    float* g0out = out + 2 * NBITS0;
    float* g1out = out + 2 * NBITS0 + NGAIN;

    const int sym0 = 2 * p;
    const size_t bbase = (size_t)bf*48 + sym0*4;     // float4-aligned (32p offset)

    if (j < 4) {
        int nib = (j == 0) ? b0A : (j == 1) ? b0B : (j == 2) ? b1A : b1B;
        float4 v = make_float4((float)( nib       & 1), (float)((nib >> 1) & 1),
                               (float)((nib >> 2) & 1), (float)((nib >> 3) & 1));
        float* base = (j < 2) ? bits0 : bits1;
        *(float4*)(base + bbase + ((j & 1) << 2)) = v;
    } else if (j == 4) {
        *(float2*)(g0out + (size_t)bf*12 + sym0) = make_float2(alpha, alpha);
    } else if (j == 5) {
        *(float2*)(g1out + (size_t)bf*12 + sym0) = make_float2(beta, beta);
    }

    if (blockIdx.x == 0 && threadIdx.x == 0)
        out[2 * (NBITS0 + NGAIN)] = 0.4f;    // nvar scalar
}

extern "C" void kernel_launch(void* const* d_in, const int* in_sizes, int n_in,
                              void* d_out, int out_size) {
    const float* ryR = (const float*)d_in[0];
    const float* ryI = (const float*)d_in[1];
    const float* hR  = (const float*)d_in[2];
    const float* hI  = (const float*)d_in[3];
    float* out = (float*)d_out;

    // total pairs = 65536*6 = 393216; 4 pairs/warp, 8 warps/block -> 12288 blocks
    const int total_pairs = BF_TOT * PAIRS;
    const int blocks = total_pairs / 32;   // 32 pairs per 256-thread block
    mc_ncjt_kernel<<<blocks, 256>>>(ryR, ryI, hR, hI, out);
}

// round 4
// speedup vs baseline: 1.3512x; 1.1662x over previous
#include <cuda_runtime.h>

// Problem constants
#define BF_TOT  (16 * 4096)      // B * F = 65536
#define PAIRS   6                // 12 data symbols -> 6 STBC pairs
#define NBITS0  3145728          // BF_TOT * 48
#define NGAIN   786432           // BF_TOT * 12

__device__ __forceinline__ float2 cmul (float2 a, float2 b){ return make_float2(a.x*b.x - a.y*b.y, a.x*b.y + a.y*b.x); }
__device__ __forceinline__ float2 cmulc(float2 a, float2 b){ /* conj(a)*b */ return make_float2(a.x*b.x + a.y*b.y, a.x*b.y - a.y*b.x); }
__device__ __forceinline__ float2 cadd (float2 a, float2 b){ return make_float2(a.x+b.x, a.y+b.y); }
__device__ __forceinline__ float2 csub (float2 a, float2 b){ return make_float2(a.x-b.x, a.y-b.y); }
__device__ __forceinline__ float2 cscl (float2 a, float s){ return make_float2(a.x*s, a.y*s); }
__device__ __forceinline__ float2 cconj(float2 a){ return make_float2(a.x, -a.y); }

// 16-QAM Gray hard decision (max-log equivalent).
__device__ __forceinline__ void hd16(float2 y, float2& pt, int& bits){
    const float C1 = 0.31622776601683794f;   // 1/sqrt(10)
    const float C3 = 0.9486832980505138f;    // 3/sqrt(10)
    const float T  = 0.6324555320336759f;    // 2/sqrt(10)
    int b0 = (y.x < 0.0f);
    int b1 = (y.y < 0.0f);
    int b2 = (fabsf(y.x) > T);
    int b3 = (fabsf(y.y) > T);
    float xi = b2 ? C3 : C1; if (b0) xi = -xi;
    float xq = b3 ? C3 : C1; if (b1) xq = -xq;
    pt = make_float2(xi, xq);
    bits = b0 | (b1 << 1) | (b2 << 2) | (b3 << 3);
}

// 3-step xor butterfly over each 8-lane group (result broadcast within group)
#define RED8(v) do { \
    v += __shfl_xor_sync(0xffffffffu, v, 1);  \
    v += __shfl_xor_sync(0xffffffffu, v, 2);  \
    v += __shfl_xor_sync(0xffffffffu, v, 4);  \
} while (0)

// Per-antenna Gram/rhs accumulation from raw channel float4s.
#define GRAM_ACC(hrA_, hiA_, hrB_, hiB_, yA_, yB_) do {                         \
    float2 a_ = make_float2(0.5f*((hrA_).x+(hrB_).x), 0.5f*((hiA_).x+(hiB_).x)); \
    float2 b_ = make_float2(0.5f*((hrA_).y+(hrB_).y), 0.5f*((hiA_).y+(hiB_).y)); \
    float2 c_ = make_float2(0.5f*((hrA_).z+(hrB_).z), 0.5f*((hiA_).z+(hiB_).z)); \
    float2 d_ = make_float2(0.5f*((hrA_).w+(hrB_).w), 0.5f*((hiA_).w+(hiB_).w)); \
    alpha += a_.x*a_.x + a_.y*a_.y + b_.x*b_.x + b_.y*b_.y;                      \
    beta  += c_.x*c_.x + c_.y*c_.y + d_.x*d_.x + d_.y*d_.y;                      \
    gam = cadd(gam, cadd(cmulc(a_, c_), cmul(b_, cconj(d_))));                   \
    del = cadd(del, csub(cmulc(a_, d_), cmul(b_, cconj(c_))));                   \
    float2 z2_ = cconj(yB_);                                                     \
    u0 = cadd(u0, cadd(cmulc(a_, (yA_)), cmul(b_, z2_)));                        \
    u1 = cadd(u1, csub(cmulc(b_, (yA_)), cmul(a_, z2_)));                        \
    u2 = cadd(u2, cadd(cmulc(c_, (yA_)), cmul(d_, z2_)));                        \
    u3 = cadd(u3, csub(cmulc(d_, (yA_)), cmul(c_, z2_)));                        \
} while (0)

// Per-antenna SIC from (reloaded) raw channel float4s.
#define SIC_ACC(hrA_, hiA_, hrB_, hiB_, yA_, yB_) do {                           \
    float2 cbA0_, cbA1_, cbB0_, cbB1_, g0_, g1_;                                 \
    if (c0) {                                                                    \
        cbA0_ = make_float2((hrA_).x, (hiA_).x); cbA1_ = make_float2((hrA_).y, (hiA_).y); \
        cbB0_ = make_float2((hrB_).x, (hiB_).x); cbB1_ = make_float2((hrB_).y, (hiB_).y); \
        g0_ = make_float2(0.5f*((hrA_).z+(hrB_).z), 0.5f*((hiA_).z+(hiB_).z));   \
        g1_ = make_float2(0.5f*((hrA_).w+(hrB_).w), 0.5f*((hiA_).w+(hiB_).w));   \
    } else {                                                                     \
        cbA0_ = make_float2((hrA_).z, (hiA_).z); cbA1_ = make_float2((hrA_).w, (hiA_).w); \
        cbB0_ = make_float2((hrB_).z, (hiB_).z); cbB1_ = make_float2((hrB_).w, (hiB_).w); \
        g0_ = make_float2(0.5f*((hrA_).x+(hrB_).x), 0.5f*((hiA_).x+(hiB_).x));   \
        g1_ = make_float2(0.5f*((hrA_).y+(hrB_).y), 0.5f*((hiA_).y+(hiB_).y));   \
    }                                                                            \
    float2 eA_ = cadd(cmul(cbA0_, bx0), cmul(cbA1_, bx1));                       \
    float2 eB_ = cadd(cmul(cbB0_, mcbx1), cmul(cbB1_, cbx0));                    \
    float2 rnA_ = csub((yA_), eA_);                                              \
    float2 rnBc_ = cconj(csub((yB_), eB_));                                      \
    t0 = cadd(t0, cadd(cmulc(g0_, rnA_), cmul(g1_, rnBc_)));                     \
    t1 = cadd(t1, csub(cmulc(g1_, rnA_), cmul(g0_, rnBc_)));                     \
} while (0)

__global__ void __launch_bounds__(256, 3)
mc_ncjt_kernel(const float* __restrict__ ryR, const float* __restrict__ ryI,
               const float* __restrict__ hR,  const float* __restrict__ hI,
               float* __restrict__ out)
{
    // Per-thread stash of raw channel data (frees 32 regs across the reduction).
    // Pad to 9 float4 (144B stride) so LDS.128/STS.128 8-lane phases are
    // bank-conflict-free: bank(lane) = (36*lane + 4k) % 32, distinct per phase.
    __shared__ float4 stash[256][9];

    const int tid  = threadIdx.x;
    const int lane = tid & 31;
    const int warp = blockIdx.x * (blockDim.x >> 5) + (tid >> 5);
    const int q    = lane >> 3;       // which pair within the warp (4 pairs/warp)
    const int j    = lane & 7;        // 8 lanes per pair; lane owns antennas j and j+8

    const int P  = warp * 4 + q;      // global STBC-pair index, exact grid
    const int bf = P / PAIRS;
    const int p  = P - bf * PAIRS;

    // data-symbol pairs: (0,1)(3,4)(5,6)(7,8)(9,10)(12,13)
    const int sA = 2*p + (p >= 1) + (p >= 5);
    const int sB = sA + 1;

    // ---- load both antennas' raw channel + received symbols ----
    const float4* hR4 = (const float4*)hR;
    const float4* hI4 = (const float4*)hI;
    const size_t h4base = (size_t)bf * 224;          // bf * S*NRX*NTX / 4
    const size_t iA = h4base + (size_t)sA*16 + j;
    const size_t iB = h4base + (size_t)sB*16 + j;
    const size_t rb = (size_t)bf * 224;              // bf * S*NRX
    float2 yA0 = make_float2(ryR[rb + sA*16 + j],     ryI[rb + sA*16 + j]);
    float2 yA1 = make_float2(ryR[rb + sA*16 + j + 8], ryI[rb + sA*16 + j + 8]);
    float2 yB0 = make_float2(ryR[rb + sB*16 + j],     ryI[rb + sB*16 + j]);
    float2 yB1 = make_float2(ryR[rb + sB*16 + j + 8], ryI[rb + sB*16 + j + 8]);

    float alpha = 0.f, beta = 0.f;
    float2 gam = make_float2(0,0), del = make_float2(0,0);
    float2 u0 = make_float2(0,0), u1 = make_float2(0,0);
    float2 u2 = make_float2(0,0), u3 = make_float2(0,0);

    {   // scope raw h so the registers die after Gram accumulation
        float4 hrA0 = hR4[iA],     hrA1 = hR4[iA + 8];
        float4 hiA0 = hI4[iA],     hiA1 = hI4[iA + 8];
        float4 hrB0 = hR4[iB],     hrB1 = hR4[iB + 8];
        float4 hiB0 = hI4[iB],     hiB1 = hI4[iB + 8];
        stash[tid][0] = hrA0; stash[tid][1] = hiA0;
        stash[tid][2] = hrB0; stash[tid][3] = hiB0;
        stash[tid][4] = hrA1; stash[tid][5] = hiA1;
        stash[tid][6] = hrB1; stash[tid][7] = hiB1;
        GRAM_ACC(hrA0, hiA0, hrB0, hiB0, yA0, yB0);
        GRAM_ACC(hrA1, hiA1, hrB1, hiB1, yA1, yB1);
    }

    // ---- 8-lane reductions (broadcast within pair group) ----
    RED8(alpha); RED8(beta);
    RED8(gam.x); RED8(gam.y); RED8(del.x); RED8(del.y);
    RED8(u0.x);  RED8(u0.y);  RED8(u1.x);  RED8(u1.y);
    RED8(u2.x);  RED8(u2.y);  RED8(u3.x);  RED8(u3.y);

    // ---- closed-form Schur solve of the structured 4x4 system ----
    const float e      = gam.x*gam.x + gam.y*gam.y + del.x*del.x + del.y*del.y;
    const float invden = 1.0f / (alpha * beta - e);
    const float invA   = 1.0f / alpha;
    float2 t2 = csub(cscl(u2, alpha), csub(cmulc(gam, u0), cmul(del, u1)));
    float2 t3 = csub(cscl(u3, alpha), cadd(cmulc(del, u0), cmul(gam, u1)));
    float2 s2 = cscl(t2, invden);
    float2 s3 = cscl(t3, invden);
    float2 s0 = cscl(csub(u0, cadd(cmul(gam, s2), cmul(del, s3))), invA);
    float2 s1 = cscl(cadd(u1, csub(cmul(cconj(del), s2), cmul(cconj(gam), s3))), invA);

    const bool c0 = (alpha >= beta);

    float2 px0, px1, px2, px3; int ib0, ib1, ib2, ib3;
    hd16(s0, px0, ib0); hd16(s1, px1, ib1);
    hd16(s2, px2, ib2); hd16(s3, px3, ib3);

    float2 bx0 = c0 ? px0 : px2;     // better-stream decisions (sym A, sym B)
    float2 bx1 = c0 ? px1 : px3;
    float2 mcbx1 = make_float2(-bx1.x, bx1.y);     // -conj(bx1)
    float2 cbx0  = cconj(bx0);

    // ---- SIC over this lane's 2 antennas (raw h reloaded from smem) ----
    float2 t0 = make_float2(0,0), t1 = make_float2(0,0);
    {
        float4 hrA0 = stash[tid][0], hiA0 = stash[tid][1];
        float4 hrB0 = stash[tid][2], hiB0 = stash[tid][3];
        SIC_ACC(hrA0, hiA0, hrB0, hiB0, yA0, yB0);
    }
    {
        float4 hrA1 = stash[tid][4], hiA1 = stash[tid][5];
        float4 hrB1 = stash[tid][6], hiB1 = stash[tid][7];
        SIC_ACC(hrA1, hiA1, hrB1, hiB1, yA1, yB1);
    }
    RED8(t0.x); RED8(t0.y); RED8(t1.x); RED8(t1.y);

    const float invG = 1.0f / (c0 ? beta : alpha);
    float2 pn0, pn1; int ibn0, ibn1;
    hd16(cscl(t0, invG), pn0, ibn0);
    hd16(cscl(t1, invG), pn1, ibn1);

    // final stream assignments
    const int bb0 = c0 ? ib0 : ib2;   // better bits sym A
    const int bb1 = c0 ? ib1 : ib3;   // better bits sym B
    const int b0A = c0 ? bb0  : ibn0; // bits0 (stream 0)
    const int b0B = c0 ? bb1  : ibn1;
    const int b1A = c0 ? ibn0 : bb0;  // bits1 (stream 1)
    const int b1B = c0 ? ibn1 : bb1;

    // ---- outputs: bits0 | bits1 | gains0 | gains1 | nvar ----
    float* bits0 = out;
    float* bits1 = out + NBITS0;
    float* g0out = out + 2 * NBITS0;
    float* g1out = out + 2 * NBITS0 + NGAIN;

    const int sym0 = 2 * p;
    const size_t bbase = (size_t)bf*48 + sym0*4;     // float4-aligned

    if (j < 4) {
        int nib = (j == 0) ? b0A : (j == 1) ? b0B : (j == 2) ? b1A : b1B;
        float4 v = make_float4((float)( nib       & 1), (float)((nib >> 1) & 1),
                               (float)((nib >> 2) & 1), (float)((nib >> 3) & 1));
        float* base = (j < 2) ? bits0 : bits1;
        *(float4*)(base + bbase + ((j & 1) << 2)) = v;
    } else if (j == 4) {
        *(float2*)(g0out + (size_t)bf*12 + sym0) = make_float2(alpha, alpha);
    } else if (j == 5) {
        *(float2*)(g1out + (size_t)bf*12 + sym0) = make_float2(beta, beta);
    }

    if (blockIdx.x == 0 && threadIdx.x == 0)
        out[2 * (NBITS0 + NGAIN)] = 0.4f;    // nvar scalar
}

extern "C" void kernel_launch(void* const* d_in, const int* in_sizes, int n_in,
                              void* d_out, int out_size) {
    const float* ryR = (const float*)d_in[0];
    const float* ryI = (const float*)d_in[1];
    const float* hR  = (const float*)d_in[2];
    const float* hI  = (const float*)d_in[3];
    float* out = (float*)d_out;

    // total pairs = 65536*6 = 393216; 4 pairs/warp, 8 warps/block -> 12288 blocks
    const int total_pairs = BF_TOT * PAIRS;
    const int blocks = total_pairs / 32;   // 32 pairs per 256-thread block
    mc_ncjt_kernel<<<blocks, 256>>>(ryR, ryI, hR, hI, out);
}